// round 2
// baseline (speedup 1.0000x reference)
#include <cuda_runtime.h>
#include <cuda_bf16.h>

// Problem constants (fixed by setup_inputs)
constexpr int L  = 4;
constexpr int Bn = 32;
constexpr int S  = 512;
constexpr int D  = 768;
constexpr int D4 = D / 4;          // 192 float4 per row
constexpr int T  = 32;             // output rows per block
constexpr int RMAX = T + 3;        // smem tile rows (halo of 3: k <= 3)
constexpr int NTHREADS = 512;
constexpr int SMEM_BYTES = RMAX * D * (int)sizeof(float);  // 107,520 B -> 2 CTAs/SM

__global__ __launch_bounds__(NTHREADS, 2)
void lmenc_span_pool_kernel(const float* __restrict__ hidden,
                            const int*   __restrict__ spans,
                            const int*   __restrict__ masks,
                            float*       __restrict__ out)
{
    extern __shared__ float4 s_x[];            // [RMAX * D4]  pooled x_lm tile
    __shared__ int s_cnt[T];
    __shared__ int s_part[NTHREADS / 32];
    __shared__ int s_mlen;

    const int b   = blockIdx.y;
    const int t0  = blockIdx.x * T;
    const int tid = threadIdx.x;

    // ---- mask_len[b] = sum(masks[b,:]) -------------------------------------
    {
        int mv = 0;
        for (int i = tid; i < S; i += NTHREADS) mv += masks[b * S + i];
        #pragma unroll
        for (int o = 16; o > 0; o >>= 1) mv += __shfl_down_sync(0xFFFFFFFFu, mv, o);
        if ((tid & 31) == 0) s_part[tid >> 5] = mv;
    }
    __syncthreads();
    if (tid == 0) {
        int s = 0;
        #pragma unroll
        for (int w = 0; w < NTHREADS / 32; w++) s += s_part[w];
        s_mlen = s;   // ordered before the next __syncthreads()
    }

    // ---- build x_lm tile: rows [t0+1, min(t0+RMAX, S-1)] -------------------
    // x_lm[s, d] = 0.25 * sum_l hidden[l, b, s, d]
    const int R = min(RMAX, S - 1 - t0);       // rows actually needed/available
    const long long slabStride = (long long)Bn * S * D4;   // float4 stride between L slices
    const long long base = ((long long)b * S + (t0 + 1)) * D4;
    const float4* __restrict__ h4 = (const float4*)hidden;

    const int total = R * D4;
    for (int i = tid; i < total; i += NTHREADS) {
        float4 a0 = h4[base + i];
        float4 a1 = h4[base + slabStride + i];
        float4 a2 = h4[base + 2 * slabStride + i];
        float4 a3 = h4[base + 3 * slabStride + i];
        float4 r;
        r.x = (a0.x + a1.x + a2.x + a3.x) * 0.25f;
        r.y = (a0.y + a1.y + a2.y + a3.y) * 0.25f;
        r.z = (a0.z + a1.z + a2.z + a3.z) * 0.25f;
        r.w = (a0.w + a1.w + a2.w + a3.w) * 0.25f;
        s_x[i] = r;
    }
    __syncthreads();   // s_x and s_mlen ready

    // ---- per-row valid-k count ---------------------------------------------
    if (tid < T) {
        const int t = t0 + tid;
        int span = 0;
        if (t + 1 < S) span = spans[b * S + t + 1];  // span_next (padded 0 at t=S-1)
        if (t >= s_mlen - 2) span = 0;               // t < mask_len - 2 required
        int c = min(span, S - 1 - t);                // enforce idx = t+1+k < S
        c = max(c, 0);
        c = min(c, 4);                               // MAX_SPAN
        s_cnt[tid] = c;
    }
    __syncthreads();

    // ---- pooled output write ------------------------------------------------
    float4* __restrict__ o4 = (float4*)out;
    const long long obase = ((long long)b * S + t0) * D4;
    for (int i = tid; i < T * D4; i += NTHREADS) {
        const int tt = i / D4;
        const int d4 = i - tt * D4;
        const int c  = s_cnt[tt];
        float4 acc = make_float4(0.f, 0.f, 0.f, 0.f);
        #pragma unroll
        for (int k = 0; k < 4; k++) {
            if (k < c) {
                // smem row index = (t+1+k) - (t0+1) = tt + k
                float4 v = s_x[(tt + k) * D4 + d4];
                acc.x += v.x; acc.y += v.y; acc.z += v.z; acc.w += v.w;
            }
        }
        o4[obase + i] = acc;   // zero rows are written too (d_out is poisoned)
    }
}

extern "C" void kernel_launch(void* const* d_in, const int* in_sizes, int n_in,
                              void* d_out, int out_size)
{
    const float* hidden = (const float*)d_in[0];
    const int*   spans  = (const int*)d_in[1];
    const int*   masks  = (const int*)d_in[2];
    float*       out    = (float*)d_out;

    // Opt in to >48KB dynamic shared memory (device-function attribute, not a
    // stream op; safe under graph capture).
    cudaFuncSetAttribute(lmenc_span_pool_kernel,
                         cudaFuncAttributeMaxDynamicSharedMemorySize, SMEM_BYTES);

    dim3 grid(S / T, Bn, 1);   // (16, 32)
    lmenc_span_pool_kernel<<<grid, NTHREADS, SMEM_BYTES>>>(hidden, spans, masks, out);
}

// round 3
// speedup vs baseline: 1.2860x; 1.2860x over previous
#include <cuda_runtime.h>
#include <cuda_bf16.h>

// Problem constants (fixed by setup_inputs)
constexpr int L  = 4;
constexpr int Bn = 32;
constexpr int S  = 512;
constexpr int D  = 768;
constexpr int D4 = D / 4;          // 192 float4 per row
constexpr int T  = 32;             // output rows per block strip (multiple of 4)
constexpr int NT = 192;            // one thread per float4 column

__device__ __forceinline__ float4 f4zero() { return make_float4(0.f, 0.f, 0.f, 0.f); }
__device__ __forceinline__ void f4add(float4& a, const float4& b) {
    a.x += b.x; a.y += b.y; a.z += b.z; a.w += b.w;
}

__global__ __launch_bounds__(NT, 4)
void lmenc_window_kernel(const float* __restrict__ hidden,
                         const int*   __restrict__ spans,
                         const int*   __restrict__ masks,
                         float*       __restrict__ out)
{
    const int b   = blockIdx.y;
    const int t0  = blockIdx.x * T;        // t0 % 4 == 0
    const int tid = threadIdx.x;           // = d4 column

    // ---- mask_len[b] (one cheap barrier, start of kernel) ------------------
    __shared__ int s_part[NT / 32];
    {
        int mv = 0;
        for (int i = tid; i < S; i += NT) mv += masks[b * S + i];
        #pragma unroll
        for (int o = 16; o > 0; o >>= 1) mv += __shfl_down_sync(0xFFFFFFFFu, mv, o);
        if ((tid & 31) == 0) s_part[tid >> 5] = mv;
    }
    __syncthreads();
    int mlen = 0;
    #pragma unroll
    for (int w = 0; w < NT / 32; w++) mlen += s_part[w];

    // ---- streaming pointers -------------------------------------------------
    const float4* __restrict__ h4 = (const float4*)hidden;
    float4*       __restrict__ o4 = (float4*)out;
    const long long slab    = (long long)Bn * S * D4;          // between L slices
    const long long rowBase = (long long)b * S * D4 + tid;     // + r*D4 per row
    const int*     spanRow  = spans + b * S;

    // pooled x_lm row r (zero if r >= S; such rows are never summed anyway)
    auto loadRow = [&](int r) -> float4 {
        float4 v = f4zero();
        if (r < S) {
            const long long p = rowBase + (long long)r * D4;
            float4 a0 = h4[p];
            float4 a1 = h4[p + slab];
            float4 a2 = h4[p + 2 * slab];
            float4 a3 = h4[p + 3 * slab];
            v.x = (a0.x + a1.x + a2.x + a3.x) * 0.25f;
            v.y = (a0.y + a1.y + a2.y + a3.y) * 0.25f;
            v.z = (a0.z + a1.z + a2.z + a3.z) * 0.25f;
            v.w = (a0.w + a1.w + a2.w + a3.w) * 0.25f;
        }
        return v;
    };

    // valid-k count for output row t
    auto cnt = [&](int t) -> int {
        int span = (t + 1 < S) ? __ldg(&spanRow[t + 1]) : 0;   // span_next
        int c = min(span, S - 1 - t);                          // idx < S
        c = max(c, 0);
        c = min(c, 4);
        if (t >= mlen - 2) c = 0;                              // t < mask_len - 2
        return c;
    };

    // ---- 4-deep register window, slot = row & 3 ----------------------------
    // Prologue: rows t0+1 .. t0+3  (slots 1,2,3 since t0 % 4 == 0)
    float4 w0 = f4zero();
    float4 w1 = loadRow(t0 + 1);
    float4 w2 = loadRow(t0 + 2);
    float4 w3 = loadRow(t0 + 3);

    // emit out[t]; window holds rows t+1..t+3, loads row t+4 into `cur`
    auto step = [&](int t, float4& cur, const float4& p1, const float4& p2,
                    const float4& p3) {
        cur = loadRow(t + 4);
        const int c = cnt(t);
        float4 acc = f4zero();
        if (c > 0) f4add(acc, p1);
        if (c > 1) f4add(acc, p2);
        if (c > 2) f4add(acc, p3);
        if (c > 3) f4add(acc, cur);
        o4[rowBase + (long long)t * D4] = acc;   // write zeros too (out poisoned)
    };

    #pragma unroll
    for (int jj = 0; jj < T; jj += 4) {
        const int tb = t0 + jj;                  // tb % 4 == 0
        step(tb + 0, w0, w1, w2, w3);            // row tb+4 -> slot 0
        step(tb + 1, w1, w2, w3, w0);            // row tb+5 -> slot 1
        step(tb + 2, w2, w3, w0, w1);            // row tb+6 -> slot 2
        step(tb + 3, w3, w0, w1, w2);            // row tb+7 -> slot 3
    }
}

extern "C" void kernel_launch(void* const* d_in, const int* in_sizes, int n_in,
                              void* d_out, int out_size)
{
    const float* hidden = (const float*)d_in[0];
    const int*   spans  = (const int*)d_in[1];
    const int*   masks  = (const int*)d_in[2];
    float*       out    = (float*)d_out;

    dim3 grid(S / T, Bn, 1);   // (16, 32) = 512 blocks
    lmenc_window_kernel<<<grid, NT>>>(hidden, spans, masks, out);
}